// round 5
// baseline (speedup 1.0000x reference)
#include <cuda_runtime.h>
#include <math.h>

#define NB   2
#define CI_  256      // output channels of deform conv / input channels of transconv
#define CO_  128      // channels of up
#define H0   64
#define W0   64
#define HH   128
#define WW   128
#define KKT  9
#define KGEMM (CO_*KKT)   // 1152
#define HW   (HH*WW)      // 16384

// ---- scratch (device globals; no allocations anywhere) ----
__device__ float g_up[NB*CO_*HH*WW];          // 16 MB
__device__ float g_S [(size_t)NB*CO_*KKT*HH*WW]; // 151 MB
__device__ float g_A [KGEMM*CI_];             // 1.18 MB, layout [k][o]
__device__ int   g_ab[NB*KKT*2];
__device__ float g_w4[NB*KKT*4];

// ============================================================
// 1) offsets: two center-tap matvecs + tanh -> per-(n,kk) bilinear table
// ============================================================
__global__ void offset_kernel(const float* __restrict__ lat_g,
                              const float* __restrict__ w1,
                              const float* __restrict__ b1,
                              const float* __restrict__ w2,
                              const float* __restrict__ b2) {
    __shared__ float lat[NB*CO_];     // 256
    __shared__ float hsm[NB*64];
    __shared__ float off[NB*18];
    int t = threadIdx.x;
    if (t < NB*CO_) lat[t] = lat_g[t];
    __syncthreads();
    if (t < NB*64) {
        int n = t >> 6, c = t & 63;
        float s = b1[c];
        const float* lp = &lat[n*CO_];
        #pragma unroll 4
        for (int i = 0; i < CO_; i++) s += lp[i] * w1[c*(CO_*9) + i*9 + 4];
        hsm[t] = fmaxf(s, 0.f);
    }
    __syncthreads();
    if (t < NB*18) {
        int n = t / 18, j = t % 18;
        float s = b2[j];
        const float* hp = &hsm[n*64];
        #pragma unroll 4
        for (int c = 0; c < 64; c++) s += hp[c] * w2[j*(64*9) + c*9 + 4];
        off[n*18 + j] = tanhf(s);
    }
    __syncthreads();
    if (t < NB*KKT) {
        int n  = t / KKT;
        int kk = t % KKT;
        int ky = kk / 3, kx = kk % 3;
        float oy = off[n*18 + kk*2 + 0];
        float ox = off[n*18 + kk*2 + 1];
        float fy = floorf(oy), fx = floorf(ox);
        float dy = oy - fy,    dx = ox - fx;
        g_ab[t*2+0] = ky - 1 + (int)fy;
        g_ab[t*2+1] = kx - 1 + (int)fx;
        g_w4[t*4+0] = (1.f-dy)*(1.f-dx);
        g_w4[t*4+1] = (1.f-dy)*dx;
        g_w4[t*4+2] = dy*(1.f-dx);
        g_w4[t*4+3] = dy*dx;
    }
}

// ============================================================
// 2) repack trans_w [o][c][kk] -> A'[k=c*9+kk][o]  (o contiguous)
// ============================================================
__global__ void repack_kernel(const float* __restrict__ tw) {
    int k = blockIdx.x;        // 0..1151
    int o = threadIdx.x;       // 0..255
    g_A[k*CI_ + o] = tw[o*KGEMM + k];
}

// ============================================================
// 3) transposed conv (stride 2, pad 1, out_pad 1) -> g_up
//    parity decomposition: each thread computes 2 output quads (2x2 each)
//    up[2y' ,2x' ]  = A*w4
//    up[2y' ,2x'+1] = B*w3 + A*w5
//    up[2y'+1,2x' ] = C*w1 + A*w7
//    up[2y'+1,2x'+1]= D*w0 + C*w2 + B*w6 + A*w8
//    A=x[y'][x'] B=x[y'][x'+1] C=x[y'+1][x'] D=x[y'+1][x'+1] (zero-padded)
// ============================================================
__global__ __launch_bounds__(128) void transconv_kernel(const float* __restrict__ x,
                                                        const float* __restrict__ tw) {
    __shared__ float xs[8][17][18];   // CI_T=8, 16+1 quad halo, padded cols
    __shared__ float ws[8][8][9];     // [ci][co][tap]
    int n    = blockIdx.z;
    int cob  = blockIdx.y;            // 16 co-blocks of 8
    int tile = blockIdx.x;            // 16 spatial tiles (quad space 64x64 / 16x16)
    int ty0 = (tile >> 2) * 16;
    int tx0 = (tile &  3) * 16;
    int t = threadIdx.x;
    int qx = t & 15, qyb = t >> 4;    // qyb 0..7, thread owns qy=qyb and qy=qyb+8

    float acc[2][8][4];
    #pragma unroll
    for (int q = 0; q < 2; q++)
        #pragma unroll
        for (int co = 0; co < 8; co++)
            #pragma unroll
            for (int s = 0; s < 4; s++) acc[q][co][s] = 0.f;

    for (int cic = 0; cic < CI_; cic += 8) {
        for (int l = t; l < 8*17*17; l += 128) {
            int ci = l / 289, rem = l % 289, r = rem / 17, s = rem % 17;
            int yy = ty0 + r, xx = tx0 + s;
            float v = 0.f;
            if (yy < H0 && xx < W0)
                v = x[((n*CI_ + cic + ci)*H0 + yy)*W0 + xx];
            xs[ci][r][s] = v;
        }
        for (int l = t; l < 8*8*9; l += 128) {
            int ci = l / 72, rem = l % 72, co = rem / 9, tap = rem % 9;
            ws[ci][co][tap] = tw[(cic+ci)*KGEMM + (cob*8+co)*9 + tap];
        }
        __syncthreads();

        #pragma unroll
        for (int ci = 0; ci < 8; ci++) {
            float Av[2], Bv[2], Cv[2], Dv[2];
            #pragma unroll
            for (int q = 0; q < 2; q++) {
                int qy = qyb + q*8;
                Av[q] = xs[ci][qy  ][qx  ];
                Bv[q] = xs[ci][qy  ][qx+1];
                Cv[q] = xs[ci][qy+1][qx  ];
                Dv[q] = xs[ci][qy+1][qx+1];
            }
            #pragma unroll
            for (int co = 0; co < 8; co++) {
                float u0 = ws[ci][co][0], u1 = ws[ci][co][1], u2 = ws[ci][co][2];
                float u3 = ws[ci][co][3], u4 = ws[ci][co][4], u5 = ws[ci][co][5];
                float u6 = ws[ci][co][6], u7 = ws[ci][co][7], u8 = ws[ci][co][8];
                #pragma unroll
                for (int q = 0; q < 2; q++) {
                    acc[q][co][0] = fmaf(Av[q], u4, acc[q][co][0]);
                    acc[q][co][1] = fmaf(Bv[q], u3, fmaf(Av[q], u5, acc[q][co][1]));
                    acc[q][co][2] = fmaf(Cv[q], u1, fmaf(Av[q], u7, acc[q][co][2]));
                    acc[q][co][3] = fmaf(Dv[q], u0, fmaf(Cv[q], u2,
                                    fmaf(Bv[q], u6, fmaf(Av[q], u8, acc[q][co][3]))));
                }
            }
        }
        __syncthreads();
    }

    #pragma unroll
    for (int q = 0; q < 2; q++) {
        int Y = (ty0 + qyb + q*8) * 2;
        int X = (tx0 + qx) * 2;
        #pragma unroll
        for (int co = 0; co < 8; co++) {
            float* up = &g_up[((n*CO_ + cob*8+co)*HH + Y)*WW + X];
            float2 r0 = make_float2(acc[q][co][0], acc[q][co][1]);
            float2 r1 = make_float2(acc[q][co][2], acc[q][co][3]);
            *(float2*)(up)       = r0;
            *(float2*)(up + WW)  = r1;
        }
    }
}

// ============================================================
// 4) build S[n][c][kk][y][x] = bilinear-const-shift sample of up (zero-padded)
// ============================================================
__global__ void build_s_kernel() {
    int nc = blockIdx.z;               // n*128 + c
    int n  = nc >> 7;
    int kk = blockIdx.y;
    int t  = threadIdx.x;              // 256
    int y  = blockIdx.x*2 + (t >> 7);
    int x  = t & 127;
    int id = n*KKT + kk;
    int a = g_ab[id*2], b = g_ab[id*2+1];
    float w00 = g_w4[id*4+0], w01 = g_w4[id*4+1];
    float w10 = g_w4[id*4+2], w11 = g_w4[id*4+3];
    const float* up = &g_up[(size_t)nc*HW];
    int yy = y + a, xx = x + b;
    float v00=0.f, v01=0.f, v10=0.f, v11=0.f;
    bool y0ok = (unsigned)yy     < (unsigned)HH;
    bool y1ok = (unsigned)(yy+1) < (unsigned)HH;
    bool x0ok = (unsigned)xx     < (unsigned)WW;
    bool x1ok = (unsigned)(xx+1) < (unsigned)WW;
    if (y0ok && x0ok) v00 = up[yy*WW + xx];
    if (y0ok && x1ok) v01 = up[yy*WW + xx + 1];
    if (y1ok && x0ok) v10 = up[(yy+1)*WW + xx];
    if (y1ok && x1ok) v11 = up[(yy+1)*WW + xx + 1];
    g_S[((size_t)nc*KKT + kk)*HW + y*WW + x] =
        fmaf(w00, v00, fmaf(w01, v01, fmaf(w10, v10, w11*v11)));
}

// ============================================================
// 5) GEMM: out[n][o][p] = sum_k A'[k][o] * S[n][k][p]
//    M=256, N=16384, K=1152 per batch. 64x128 block tile, 8x8 thread tile.
// ============================================================
__global__ __launch_bounds__(128) void gemm_kernel(float* __restrict__ out) {
    __shared__ float As[16][64];
    __shared__ float Bs[16][128];
    int n  = blockIdx.z;
    int ob = blockIdx.y;               // 4 o-blocks of 64
    int pb = blockIdx.x;               // 128 p-blocks of 128
    int t  = threadIdx.x;
    int tx = t & 15, ty = t >> 4;      // 16 x 8
    const float* Ag = g_A + ob*64;
    const float* Bg = g_S + (size_t)n*KGEMM*HW + pb*128;

    float acc[8][8];
    #pragma unroll
    for (int i = 0; i < 8; i++)
        #pragma unroll
        for (int j = 0; j < 8; j++) acc[i][j] = 0.f;

    for (int k0 = 0; k0 < KGEMM; k0 += 16) {
        #pragma unroll
        for (int i = 0; i < 2; i++) {
            int f4 = t + i*128;                   // 256 float4
            int r = f4 >> 4, c4 = (f4 & 15) << 2;
            *(float4*)&As[r][c4] = *(const float4*)(Ag + (k0+r)*CI_ + c4);
        }
        #pragma unroll
        for (int i = 0; i < 4; i++) {
            int f4 = t + i*128;                   // 512 float4
            int r = f4 >> 5, c4 = (f4 & 31) << 2;
            *(float4*)&Bs[r][c4] = *(const float4*)(Bg + (size_t)(k0+r)*HW + c4);
        }
        __syncthreads();
        #pragma unroll
        for (int k = 0; k < 16; k++) {
            float a[8], b[8];
            *(float4*)&a[0] = *(float4*)&As[k][ty*4];
            *(float4*)&a[4] = *(float4*)&As[k][32 + ty*4];
            *(float4*)&b[0] = *(float4*)&Bs[k][tx*4];
            *(float4*)&b[4] = *(float4*)&Bs[k][64 + tx*4];
            #pragma unroll
            for (int i = 0; i < 8; i++)
                #pragma unroll
                for (int j = 0; j < 8; j++)
                    acc[i][j] = fmaf(a[i], b[j], acc[i][j]);
        }
        __syncthreads();
    }

    #pragma unroll
    for (int i = 0; i < 8; i++) {
        int o = ob*64 + ((i < 4) ? (ty*4 + i) : (32 + ty*4 + i - 4));
        float* orow = out + ((size_t)(n*CI_ + o))*HW + pb*128;
        *(float4*)(orow + tx*4)      = *(float4*)&acc[i][0];
        *(float4*)(orow + 64 + tx*4) = *(float4*)&acc[i][4];
    }
}

// ============================================================
extern "C" void kernel_launch(void* const* d_in, const int* in_sizes, int n_in,
                              void* d_out, int out_size) {
    const float* x   = (const float*)d_in[0];  // [2,256,64,64]
    const float* lat = (const float*)d_in[1];  // [2,128,1,1]
    const float* tw  = (const float*)d_in[2];  // [256,128,3,3]
    const float* w1  = (const float*)d_in[3];  // [64,128,3,3]
    const float* b1  = (const float*)d_in[4];  // [64]
    const float* w2  = (const float*)d_in[5];  // [18,64,3,3]
    const float* b2  = (const float*)d_in[6];  // [18]
    float* out = (float*)d_out;                // [2,256,128,128]

    offset_kernel<<<1, 256>>>(lat, w1, b1, w2, b2);
    repack_kernel<<<KGEMM, 256>>>(tw);
    transconv_kernel<<<dim3(16, 16, NB), 128>>>(x, tw);
    build_s_kernel<<<dim3(64, KKT, NB*CO_), 256>>>();
    gemm_kernel<<<dim3(128, 4, NB), 128>>>(out);
}